// round 16
// baseline (speedup 1.0000x reference)
#include <cuda_runtime.h>
#include <math.h>

#define BATCH 8
#define CHAN 128
#define PLANE 65536            // D*H*W = 4*128*128
#define NBC (BATCH * CHAN)     // 1024
#define HALF_F4 8192           // (PLANE/4)/2 float4 per half-plane

__device__ float g_part[256];  // per-batch partial maxes (2 halves x 128 chans)
__device__ float g_gate[NBC];

// ---------------------------------------------------------------------------
// Per-batch reduce: 256 blocks x 512 threads; block j = (chan j>>1, half j&1).
// 16 f4/thread in 2 chunks of 8 front-batched loads (verified high-MLP
// pattern). Default cache policy: batch stays resident in L2 for scale_b.
// ---------------------------------------------------------------------------
__global__ __launch_bounds__(512) void reduce_b_kernel(const float* __restrict__ x,
                                                       int b) {
    const int c    = blockIdx.x >> 1;
    const int half = blockIdx.x & 1;
    const int tid  = threadIdx.x;
    const float4* p = reinterpret_cast<const float4*>(x)
                    + ((size_t)b * CHAN + c) * (PLANE / 4) + (size_t)half * HALF_F4;

    float m = -INFINITY;
    #pragma unroll
    for (int ch = 0; ch < 2; ch++) {
        const int base = ch * 4096 + tid;
        float4 v[8];
        #pragma unroll
        for (int k = 0; k < 8; k++)
            v[k] = p[base + k * 512];
        float a0 = -INFINITY, a1 = -INFINITY;
        #pragma unroll
        for (int k = 0; k < 8; k += 2) {
            a0 = fmaxf(a0, fmaxf(fmaxf(v[k].x, v[k].y), fmaxf(v[k].z, v[k].w)));
            a1 = fmaxf(a1, fmaxf(fmaxf(v[k+1].x, v[k+1].y), fmaxf(v[k+1].z, v[k+1].w)));
        }
        m = fmaxf(m, fmaxf(a0, a1));
    }

    #pragma unroll
    for (int off = 16; off > 0; off >>= 1)
        m = fmaxf(m, __shfl_xor_sync(0xffffffffu, m, off));

    __shared__ float sm[16];
    if ((tid & 31) == 0) sm[tid >> 5] = m;
    __syncthreads();
    if (tid < 16) {
        m = sm[tid];
        #pragma unroll
        for (int off = 8; off > 0; off >>= 1)
            m = fmaxf(m, __shfl_xor_sync(0x0000ffffu, m, off));
        if (tid == 0) g_part[c * 2 + half] = m;
    }
}

// ---------------------------------------------------------------------------
// Per-batch MLP gate: 1 block x 128 threads. Combines half-plane partials,
// then h = relu(W1 gp + b1), gate = sigmoid(W2 h + b2) -> g_gate[b, :].
// Weights are L2-hot after batch 0.
// ---------------------------------------------------------------------------
__global__ __launch_bounds__(128) void mlp_b_kernel(const float* __restrict__ w1,
                                                    const float* __restrict__ b1,
                                                    const float* __restrict__ w2,
                                                    const float* __restrict__ b2,
                                                    int b) {
    const int o = threadIdx.x;
    __shared__ float gp[CHAN];
    __shared__ float hs[CHAN];

    gp[o] = fmaxf(__ldcg(&g_part[2 * o]), __ldcg(&g_part[2 * o + 1]));
    __syncthreads();

    {
        float acc = __ldg(&b1[o]);
        const float4* wrow = reinterpret_cast<const float4*>(w1 + (size_t)o * CHAN);
        #pragma unroll 8
        for (int q = 0; q < CHAN / 4; q++) {
            float4 w = __ldg(wrow + q);
            const int k = q * 4;
            acc = fmaf(gp[k],     w.x, acc);
            acc = fmaf(gp[k + 1], w.y, acc);
            acc = fmaf(gp[k + 2], w.z, acc);
            acc = fmaf(gp[k + 3], w.w, acc);
        }
        hs[o] = fmaxf(acc, 0.0f);
    }
    __syncthreads();
    {
        float acc = __ldg(&b2[o]);
        const float4* wrow = reinterpret_cast<const float4*>(w2 + (size_t)o * CHAN);
        #pragma unroll 8
        for (int q = 0; q < CHAN / 4; q++) {
            float4 w = __ldg(wrow + q);
            const int k = q * 4;
            acc = fmaf(hs[k],     w.x, acc);
            acc = fmaf(hs[k + 1], w.y, acc);
            acc = fmaf(hs[k + 2], w.z, acc);
            acc = fmaf(hs[k + 3], w.w, acc);
        }
        g_gate[b * CHAN + o] = 1.0f / (1.0f + expf(-acc));
    }
}

// ---------------------------------------------------------------------------
// Per-batch scale: 1024 blocks x 256 threads x 8 f4 (verified pattern).
// Reads should hit L2 (batch b just streamed by reduce_b); __ldcs marks
// evict-first after use, freeing L2 for batch b+1. __stcs writes.
// ---------------------------------------------------------------------------
__global__ __launch_bounds__(256) void scale_b_kernel(const float* __restrict__ x,
                                                      float* __restrict__ out,
                                                      int b) {
    const int r = blockIdx.x;                    // 8 regions per plane
    const float g = g_gate[b * CHAN + (r >> 3)];
    const size_t base = ((size_t)b * CHAN) * (PLANE / 4)
                      + (size_t)r * 2048 + threadIdx.x;
    const float4* xp = reinterpret_cast<const float4*>(x);
    float4* op = reinterpret_cast<float4*>(out);

    float4 v[8];
    #pragma unroll
    for (int k = 0; k < 8; k++)
        v[k] = __ldcs(xp + base + (size_t)k * 256);

    #pragma unroll
    for (int k = 0; k < 8; k++) {
        v[k].x *= g; v[k].y *= g; v[k].z *= g; v[k].w *= g;
        __stcs(op + base + (size_t)k * 256, v[k]);
    }
}

// ---------------------------------------------------------------------------
// Pipeline: stream 0 runs reduce_b + mlp_b for b=0..7; forked stream s2 runs
// scale_b after mlp_b (event dependency), overlapping reduce_{b+1}.
// Streams/events created once on the first (uncaptured) correctness call;
// host-side objects only — no device allocation.
// ---------------------------------------------------------------------------
extern "C" void kernel_launch(void* const* d_in, const int* in_sizes, int n_in,
                              void* d_out, int out_size) {
    const float* x  = (const float*)d_in[0];
    const float* w1 = (const float*)d_in[1];
    const float* b1 = (const float*)d_in[2];
    const float* w2 = (const float*)d_in[3];
    const float* b2 = (const float*)d_in[4];
    float* out = (float*)d_out;

    static cudaStream_t s2 = nullptr;
    static cudaEvent_t evM[BATCH];
    static cudaEvent_t evJoin = nullptr;
    if (s2 == nullptr) {
        cudaStreamCreateWithFlags(&s2, cudaStreamNonBlocking);
        for (int b = 0; b < BATCH; b++)
            cudaEventCreateWithFlags(&evM[b], cudaEventDisableTiming);
        cudaEventCreateWithFlags(&evJoin, cudaEventDisableTiming);
    }

    for (int b = 0; b < BATCH; b++) {
        reduce_b_kernel<<<256, 512, 0, 0>>>(x, b);
        mlp_b_kernel<<<1, 128, 0, 0>>>(w1, b1, w2, b2, b);
        cudaEventRecord(evM[b], 0);
        cudaStreamWaitEvent(s2, evM[b], 0);
        scale_b_kernel<<<1024, 256, 0, s2>>>(x, out, b);
    }
    // join forked stream back into the capture-origin stream
    cudaEventRecord(evJoin, s2);
    cudaStreamWaitEvent(0, evJoin, 0);
}